// round 1
// baseline (speedup 1.0000x reference)
#include <cuda_runtime.h>
#include <math.h>

#define BH   32      // B*H
#define SEQ  2048
#define DIM  1024
#define NH   16
#define HDIM 64
#define MROWS 4096   // B*S

// Scratch (allocation-free rule: __device__ globals)
__device__ float g_Q[BH * SEQ * HDIM];              // [bh][s][hd], pre-scaled by 1/sqrt(HD)
__device__ float g_K[BH * SEQ * HDIM];              // [bh][s][hd]
__device__ float g_V[BH * SEQ * HDIM];              // [bh][s][hd]
__device__ float g_S[(size_t)BH * SEQ * SEQ];       // [bh][q][k] scores -> weights (in place)
__device__ float g_A[(size_t)MROWS * DIM];          // merged-head attention output

// ---------------------------------------------------------------------------
// Generic 64x64x16 fp32 GEMM: out = A[M,K] @ W[K,N] + bias, with output routing.
// asel: 0 -> use Ain, 1 -> use g_A.
// osel: 0 -> plain [M,N] into outp; 1/2/3 -> head-split into g_Q/g_K/g_V.
// ---------------------------------------------------------------------------
__global__ __launch_bounds__(256) void proj_kernel(
    const float* __restrict__ Ain, const float* __restrict__ W,
    const float* __restrict__ bias, float* __restrict__ outp,
    int asel, int osel, float scale)
{
    __shared__ float As[16][65];   // As[k][m], padded: conflict-free transposed stores
    __shared__ float Bs[16][64];   // Bs[k][n], float4 stores/loads

    const float* A = asel ? g_A : Ain;
    int tid = threadIdx.x;
    int m0 = blockIdx.y * 64;
    int n0 = blockIdx.x * 64;

    int ac  = tid & 15;        // k within tile for A loads
    int ar0 = tid >> 4;        // base row for A loads (0..15)
    int br  = tid >> 4;        // k row for B loads
    int bc  = (tid & 15) * 4;  // n col (float4) for B loads
    int tx  = tid & 15;        // n-thread
    int ty  = tid >> 4;        // m-thread

    float acc[4][4] = {};

    for (int k0 = 0; k0 < DIM; k0 += 16) {
#pragma unroll
        for (int r = 0; r < 4; r++)
            As[ac][ar0 + r * 16] = A[(size_t)(m0 + ar0 + r * 16) * DIM + k0 + ac];
        *(float4*)&Bs[br][bc] = *(const float4*)(W + (size_t)(k0 + br) * DIM + n0 + bc);
        __syncthreads();
#pragma unroll
        for (int k = 0; k < 16; k++) {
            float4 b4 = *(const float4*)&Bs[k][tx * 4];
            float ra[4];
#pragma unroll
            for (int i = 0; i < 4; i++) ra[i] = As[k][ty * 4 + i];
            float rb[4] = {b4.x, b4.y, b4.z, b4.w};
#pragma unroll
            for (int i = 0; i < 4; i++)
#pragma unroll
                for (int j = 0; j < 4; j++)
                    acc[i][j] = fmaf(ra[i], rb[j], acc[i][j]);
        }
        __syncthreads();
    }

#pragma unroll
    for (int i = 0; i < 4; i++) {
        int m = m0 + ty * 4 + i;
#pragma unroll
        for (int j = 0; j < 4; j++) {
            int n = n0 + tx * 4 + j;
            float v = (acc[i][j] + bias[n]) * scale;
            if (osel == 0) {
                outp[(size_t)m * DIM + n] = v;
            } else {
                float* dst = (osel == 1) ? g_Q : (osel == 2) ? g_K : g_V;
                int b = m >> 11, s = m & (SEQ - 1);
                int h = n >> 6,  hd = n & (HDIM - 1);
                dst[(((size_t)b * NH + h) * SEQ + s) * HDIM + hd] = v;
            }
        }
    }
}

// ---------------------------------------------------------------------------
// scores[bh][q][k] = sum_d Qs[bh][q][d] * K[bh][k][d]   (scale pre-folded in Q)
// Full HD=64 inner dim in smem, transposed tiles [d][s] for conflict-free reads.
// ---------------------------------------------------------------------------
__global__ __launch_bounds__(256) void scores_kernel()
{
    __shared__ float Qt[64][68];   // [d][q], pad 68 keeps float4 alignment
    __shared__ float Kt[64][68];   // [d][k]

    int bh = blockIdx.z;
    int m0 = blockIdx.y * 64;      // q tile
    int n0 = blockIdx.x * 64;      // k tile
    const float* Qb = g_Q + (size_t)bh * SEQ * HDIM;
    const float* Kb = g_K + (size_t)bh * SEQ * HDIM;

    int tid = threadIdx.x;
    int d  = tid & 63;
    int s0 = tid >> 6;             // 0..3
#pragma unroll
    for (int r = 0; r < 16; r++) {
        int s = s0 + r * 4;
        Qt[d][s] = Qb[(size_t)(m0 + s) * HDIM + d];
        Kt[d][s] = Kb[(size_t)(n0 + s) * HDIM + d];
    }
    __syncthreads();

    int tx = tid & 15, ty = tid >> 4;
    float acc[4][4] = {};
#pragma unroll 8
    for (int dd = 0; dd < 64; dd++) {
        float4 q4 = *(const float4*)&Qt[dd][ty * 4];
        float4 k4 = *(const float4*)&Kt[dd][tx * 4];
        float ra[4] = {q4.x, q4.y, q4.z, q4.w};
        float rb[4] = {k4.x, k4.y, k4.z, k4.w};
#pragma unroll
        for (int i = 0; i < 4; i++)
#pragma unroll
            for (int j = 0; j < 4; j++)
                acc[i][j] = fmaf(ra[i], rb[j], acc[i][j]);
    }

    float* Sb = g_S + (size_t)bh * SEQ * SEQ;
#pragma unroll
    for (int i = 0; i < 4; i++) {
        float4 o = make_float4(acc[i][0], acc[i][1], acc[i][2], acc[i][3]);
        *(float4*)(Sb + (size_t)(m0 + ty * 4 + i) * SEQ + n0 + tx * 4) = o;
    }
}

// ---------------------------------------------------------------------------
// In-place row softmax over g_S. One 256-thread block per row (2048 elems).
// ---------------------------------------------------------------------------
__global__ __launch_bounds__(256) void softmax_kernel()
{
    float* p = g_S + (size_t)blockIdx.x * SEQ;
    int tid = threadIdx.x;
    int wid = tid >> 5, lid = tid & 31;
    __shared__ float sred[8];

    float v[8];
    float mx = -1e30f;
#pragma unroll
    for (int i = 0; i < 8; i++) { v[i] = p[tid + i * 256]; mx = fmaxf(mx, v[i]); }
#pragma unroll
    for (int o = 16; o > 0; o >>= 1) mx = fmaxf(mx, __shfl_xor_sync(0xffffffffu, mx, o));
    if (lid == 0) sred[wid] = mx;
    __syncthreads();
    if (wid == 0) {
        float t = sred[lid & 7];
#pragma unroll
        for (int o = 4; o > 0; o >>= 1) t = fmaxf(t, __shfl_xor_sync(0xffffffffu, t, o));
        if (lid == 0) sred[0] = t;
    }
    __syncthreads();
    mx = sred[0];
    __syncthreads();

    float sum = 0.f;
#pragma unroll
    for (int i = 0; i < 8; i++) { v[i] = __expf(v[i] - mx); sum += v[i]; }
#pragma unroll
    for (int o = 16; o > 0; o >>= 1) sum += __shfl_xor_sync(0xffffffffu, sum, o);
    if (lid == 0) sred[wid] = sum;
    __syncthreads();
    if (wid == 0) {
        float t = sred[lid & 7];
#pragma unroll
        for (int o = 4; o > 0; o >>= 1) t += __shfl_xor_sync(0xffffffffu, t, o);
        if (lid == 0) sred[0] = t;
    }
    __syncthreads();
    float inv = 1.0f / sred[0];
#pragma unroll
    for (int i = 0; i < 8; i++) p[tid + i * 256] = v[i] * inv;
}

// ---------------------------------------------------------------------------
// attn[b, s, h*HD+hd] = sum_k weights[bh][s][k] * V[bh][k][hd]
// Batched 64x64x16 GEMM (N = HD = 64 exactly), merged-head output into g_A.
// ---------------------------------------------------------------------------
__global__ __launch_bounds__(256) void attnv_kernel()
{
    __shared__ float As[16][65];
    __shared__ float Bs[16][64];

    int bh = blockIdx.y;
    int m0 = blockIdx.x * 64;
    const float* A  = g_S + (size_t)bh * SEQ * SEQ;
    const float* Bv = g_V + (size_t)bh * SEQ * HDIM;

    int tid = threadIdx.x;
    int ac  = tid & 15;
    int ar0 = tid >> 4;
    int br  = tid >> 4;
    int bc  = (tid & 15) * 4;
    int tx  = tid & 15, ty = tid >> 4;

    float acc[4][4] = {};

    for (int k0 = 0; k0 < SEQ; k0 += 16) {
#pragma unroll
        for (int r = 0; r < 4; r++)
            As[ac][ar0 + r * 16] = A[(size_t)(m0 + ar0 + r * 16) * SEQ + k0 + ac];
        *(float4*)&Bs[br][bc] = *(const float4*)(Bv + (size_t)(k0 + br) * HDIM + bc);
        __syncthreads();
#pragma unroll
        for (int k = 0; k < 16; k++) {
            float4 b4 = *(const float4*)&Bs[k][tx * 4];
            float ra[4];
#pragma unroll
            for (int i = 0; i < 4; i++) ra[i] = As[k][ty * 4 + i];
            float rb[4] = {b4.x, b4.y, b4.z, b4.w};
#pragma unroll
            for (int i = 0; i < 4; i++)
#pragma unroll
                for (int j = 0; j < 4; j++)
                    acc[i][j] = fmaf(ra[i], rb[j], acc[i][j]);
        }
        __syncthreads();
    }

    int b = bh >> 4, h = bh & 15;
#pragma unroll
    for (int i = 0; i < 4; i++) {
        int row = b * SEQ + m0 + ty * 4 + i;
        int col = h * HDIM + tx * 4;
        float4 o = make_float4(acc[i][0], acc[i][1], acc[i][2], acc[i][3]);
        *(float4*)(g_A + (size_t)row * DIM + col) = o;
    }
}

// ---------------------------------------------------------------------------
extern "C" void kernel_launch(void* const* d_in, const int* in_sizes, int n_in,
                              void* d_out, int out_size)
{
    const float* x  = (const float*)d_in[0];
    const float* Wq = (const float*)d_in[1];
    const float* bq = (const float*)d_in[2];
    const float* Wk = (const float*)d_in[3];
    const float* bk = (const float*)d_in[4];
    const float* Wv = (const float*)d_in[5];
    const float* bv = (const float*)d_in[6];
    const float* Wo = (const float*)d_in[7];
    const float* bo = (const float*)d_in[8];
    float* out = (float*)d_out;

    dim3 blk(256);
    dim3 gproj(DIM / 64, MROWS / 64);   // 16 x 64

    // Q/K/V projections (scale 1/sqrt(64)=0.125 folded into Q)
    proj_kernel<<<gproj, blk>>>(x, Wq, bq, nullptr, 0, 1, 0.125f);
    proj_kernel<<<gproj, blk>>>(x, Wk, bk, nullptr, 0, 2, 1.0f);
    proj_kernel<<<gproj, blk>>>(x, Wv, bv, nullptr, 0, 3, 1.0f);

    // scores = Qs @ K^T
    scores_kernel<<<dim3(SEQ / 64, SEQ / 64, BH), blk>>>();

    // softmax rows
    softmax_kernel<<<BH * SEQ, blk>>>();

    // attn = weights @ V (merged-head layout)
    attnv_kernel<<<dim3(SEQ / 64, BH), blk>>>();

    // output projection
    proj_kernel<<<gproj, blk>>>(nullptr, Wo, bo, out, 1, 0, 1.0f);
}

// round 3
// speedup vs baseline: 2.1113x; 2.1113x over previous
#include <cuda_runtime.h>
#include <cuda_bf16.h>
#include <math.h>
#include <stdint.h>

#define BH    32
#define SEQ   2048
#define DIM   1024
#define NH    16
#define HDIM  64
#define MROWS 4096

// ---------------- device scratch (allocation-free rule) ----------------
__device__ __nv_bfloat16 g_xh[MROWS * DIM], g_xl[MROWS * DIM];
__device__ __nv_bfloat16 g_Wqh[DIM * DIM], g_Wql[DIM * DIM];
__device__ __nv_bfloat16 g_Wkh[DIM * DIM], g_Wkl[DIM * DIM];
__device__ __nv_bfloat16 g_Wvh[DIM * DIM], g_Wvl[DIM * DIM];
__device__ __nv_bfloat16 g_Woh[DIM * DIM], g_Wol[DIM * DIM];
__device__ __nv_bfloat16 g_Qh[BH * SEQ * HDIM], g_Ql[BH * SEQ * HDIM];   // [bh][s][hd]
__device__ __nv_bfloat16 g_Kh[BH * SEQ * HDIM], g_Kl[BH * SEQ * HDIM];   // [bh][s][hd]
__device__ __nv_bfloat16 g_Vth[BH * HDIM * SEQ], g_Vtl[BH * HDIM * SEQ]; // [bh][hd][s]
__device__ float         g_S[(size_t)BH * SEQ * SEQ];                    // fp32 scores
__device__ __nv_bfloat16 g_Ph[(size_t)BH * SEQ * SEQ], g_Pl[(size_t)BH * SEQ * SEQ];
__device__ __nv_bfloat16 g_Ah[(size_t)MROWS * DIM], g_Al[(size_t)MROWS * DIM];

// ---------------- helpers ----------------
__device__ __forceinline__ uint32_t smem_u32(const void* p) {
    uint32_t a;
    asm("{ .reg .u64 t; cvta.to.shared.u64 t, %1; cvt.u32.u64 %0, t; }" : "=r"(a) : "l"(p));
    return a;
}
__device__ __forceinline__ void cp16(uint32_t s, const void* g) {
    asm volatile("cp.async.cg.shared.global [%0], [%1], 16;" :: "r"(s), "l"(g));
}
__device__ __forceinline__ void mma_bf16(float* d, const uint32_t* a, const uint32_t* b) {
    asm volatile(
        "mma.sync.aligned.m16n8k16.row.col.f32.bf16.bf16.f32 "
        "{%0,%1,%2,%3}, {%4,%5,%6,%7}, {%8,%9}, {%0,%1,%2,%3};"
        : "+f"(d[0]), "+f"(d[1]), "+f"(d[2]), "+f"(d[3])
        : "r"(a[0]), "r"(a[1]), "r"(a[2]), "r"(a[3]), "r"(b[0]), "r"(b[1]));
}

// ---------------- split conversion kernels ----------------
__global__ __launch_bounds__(256) void split_kernel(const float* __restrict__ in,
                                                    __nv_bfloat16* __restrict__ h,
                                                    __nv_bfloat16* __restrict__ l, int n) {
    int i = blockIdx.x * 256 + threadIdx.x;
    if (i < n) {
        float v = in[i];
        __nv_bfloat16 hi = __float2bfloat16(v);
        h[i] = hi;
        l[i] = __float2bfloat16(v - __bfloat162float(hi));
    }
}

// W[k][n] -> Wt hi/lo [n][k]
__global__ __launch_bounds__(256) void wsplit_kernel(const float* __restrict__ W,
                                                     __nv_bfloat16* __restrict__ th,
                                                     __nv_bfloat16* __restrict__ tl) {
    __shared__ float t[32][33];
    int n0 = blockIdx.x * 32, k0 = blockIdx.y * 32;
    int tx = threadIdx.x & 31, ty = threadIdx.x >> 5;
#pragma unroll
    for (int r = ty; r < 32; r += 8)
        t[r][tx] = W[(size_t)(k0 + r) * DIM + n0 + tx];
    __syncthreads();
#pragma unroll
    for (int r = ty; r < 32; r += 8) {
        float v = t[tx][r];
        __nv_bfloat16 hi = __float2bfloat16(v);
        size_t idx = (size_t)(n0 + r) * DIM + k0 + tx;
        th[idx] = hi;
        tl[idx] = __float2bfloat16(v - __bfloat162float(hi));
    }
}

// ---------------- mma.sync split-bf16 GEMM ----------------
// D[m][n] = sum_k (Ah+Al)[m][k] * (Bh+Bl)[n][k], 3-term split, shared fp32 accum.
// CTA tile 128 x TN, Kc = 32, double-buffered cp.async, 8 warps (4 M x 2 N).
// modes: 0 Q/K head-split hi/lo, 1 V transposed hi/lo, 2 fp32 out (+bias),
//        3 fp32 scores (batched), 4 merged-head hi/lo (batched)
template <int TN>
__global__ __launch_bounds__(256, 1) void gemm_kernel(
    const __nv_bfloat16* __restrict__ Ah, const __nv_bfloat16* __restrict__ Al,
    long strideA, long bStrideA,
    const __nv_bfloat16* __restrict__ Bh, const __nv_bfloat16* __restrict__ Bl,
    long strideB, long bStrideB,
    const float* __restrict__ bias, float scale, int Ktot, int mode,
    __nv_bfloat16* __restrict__ outH, __nv_bfloat16* __restrict__ outL,
    float* __restrict__ outF)
{
    extern __shared__ char smem[];
    constexpr int WN  = TN / 2;     // warp N extent
    constexpr int NT  = WN / 8;     // n8 tiles per warp
    constexpr int ROWB = 80;        // bytes per smem row: 32 bf16 + 8 pad
    constexpr int A_H = 0;
    constexpr int A_L = 128 * ROWB;
    constexpr int B_H = 2 * 128 * ROWB;
    constexpr int B_L = 2 * 128 * ROWB + TN * ROWB;
    constexpr int STAGE = 2 * 128 * ROWB + 2 * TN * ROWB;

    const int tid = threadIdx.x;
    const int w = tid >> 5, lane = tid & 31;
    const int g = lane >> 2, t = lane & 3;
    const int wm = w & 3, wn = w >> 2;
    const int z = blockIdx.z;
    Ah += (size_t)z * bStrideA;  Al += (size_t)z * bStrideA;
    Bh += (size_t)z * bStrideB;  Bl += (size_t)z * bStrideB;

    const int m0 = blockIdx.y * 128, n0 = blockIdx.x * TN;
    const int nch = Ktot >> 5;
    const uint32_t sb = smem_u32(smem);

    float acc[2][NT][4];
#pragma unroll
    for (int i = 0; i < 2; i++)
#pragma unroll
        for (int j = 0; j < NT; j++)
#pragma unroll
            for (int k = 0; k < 4; k++) acc[i][j][k] = 0.f;

    auto stage_load = [&](int buf, int c) {
        const int k0 = c << 5;
        const uint32_t so = sb + buf * STAGE;
#pragma unroll
        for (int i = tid; i < 512; i += 256) {
            int r = i >> 2, cc = i & 3;
            uint32_t off = r * ROWB + cc * 16;
            const __nv_bfloat16* pa = Ah + (size_t)(m0 + r) * strideA + k0 + cc * 8;
            const __nv_bfloat16* pl = Al + (size_t)(m0 + r) * strideA + k0 + cc * 8;
            cp16(so + A_H + off, pa);
            cp16(so + A_L + off, pl);
        }
#pragma unroll
        for (int i = tid; i < TN * 4; i += 256) {
            int r = i >> 2, cc = i & 3;
            uint32_t off = r * ROWB + cc * 16;
            const __nv_bfloat16* pb = Bh + (size_t)(n0 + r) * strideB + k0 + cc * 8;
            const __nv_bfloat16* pl = Bl + (size_t)(n0 + r) * strideB + k0 + cc * 8;
            cp16(so + B_H + off, pb);
            cp16(so + B_L + off, pl);
        }
        asm volatile("cp.async.commit_group;");
    };

    stage_load(0, 0);

    for (int c = 0; c < nch; c++) {
        const int buf = c & 1;
        if (c + 1 < nch) {
            stage_load(buf ^ 1, c + 1);
            asm volatile("cp.async.wait_group 1;");
        } else {
            asm volatile("cp.async.wait_group 0;");
        }
        __syncthreads();

        const char* s = smem + buf * STAGE;
#pragma unroll
        for (int ks = 0; ks < 2; ks++) {
            const int kb = ks * 32 + t * 4;  // byte offset within row
            uint32_t ah[2][4], al[2][4], bh[NT][2], bl[NT][2];
#pragma unroll
            for (int mt = 0; mt < 2; mt++) {
                int row = wm * 32 + mt * 16 + g;
                const char* p = s + row * ROWB + kb;
                ah[mt][0] = *(const uint32_t*)(p + A_H);
                ah[mt][1] = *(const uint32_t*)(p + A_H + 8 * ROWB);
                ah[mt][2] = *(const uint32_t*)(p + A_H + 16);
                ah[mt][3] = *(const uint32_t*)(p + A_H + 8 * ROWB + 16);
                al[mt][0] = *(const uint32_t*)(p + A_L);
                al[mt][1] = *(const uint32_t*)(p + A_L + 8 * ROWB);
                al[mt][2] = *(const uint32_t*)(p + A_L + 16);
                al[mt][3] = *(const uint32_t*)(p + A_L + 8 * ROWB + 16);
            }
#pragma unroll
            for (int nt = 0; nt < NT; nt++) {
                int n = wn * WN + nt * 8 + g;
                const char* p = s + n * ROWB + kb;
                bh[nt][0] = *(const uint32_t*)(p + B_H);
                bh[nt][1] = *(const uint32_t*)(p + B_H + 16);
                bl[nt][0] = *(const uint32_t*)(p + B_L);
                bl[nt][1] = *(const uint32_t*)(p + B_L + 16);
            }
#pragma unroll
            for (int mt = 0; mt < 2; mt++)
#pragma unroll
                for (int nt = 0; nt < NT; nt++) {
                    mma_bf16(acc[mt][nt], ah[mt], bh[nt]);
                    mma_bf16(acc[mt][nt], ah[mt], bl[nt]);
                    mma_bf16(acc[mt][nt], al[mt], bh[nt]);
                }
        }
        __syncthreads();
    }

    // ---------------- epilogue ----------------
#pragma unroll
    for (int mt = 0; mt < 2; mt++)
#pragma unroll
        for (int nt = 0; nt < NT; nt++)
#pragma unroll
            for (int p = 0; p < 2; p++) {
                int row = m0 + wm * 32 + mt * 16 + g + 8 * p;
                int col = n0 + wn * WN + nt * 8 + 2 * t;
                float v0 = acc[mt][nt][2 * p + 0];
                float v1 = acc[mt][nt][2 * p + 1];
                if (mode == 0 || mode == 1) {
                    int b = row >> 11, sq = row & (SEQ - 1);
                    v0 = (v0 + bias[col]) * scale;
                    v1 = (v1 + bias[col + 1]) * scale;
#pragma unroll
                    for (int e = 0; e < 2; e++) {
                        int cc = col + e;
                        float v = e ? v1 : v0;
                        int h = cc >> 6, hd = cc & (HDIM - 1);
                        __nv_bfloat16 hi = __float2bfloat16(v);
                        __nv_bfloat16 lo = __float2bfloat16(v - __bfloat162float(hi));
                        size_t idx = (mode == 0)
                            ? ((((size_t)b * NH + h) * SEQ + sq) * HDIM + hd)
                            : ((((size_t)b * NH + h) * HDIM + hd) * SEQ + sq);
                        outH[idx] = hi;
                        outL[idx] = lo;
                    }
                } else if (mode == 2) {
                    float2 o = make_float2(v0 + bias[col], v1 + bias[col + 1]);
                    *(float2*)(outF + (size_t)row * DIM + col) = o;
                } else if (mode == 3) {
                    *(float2*)(outF + (size_t)z * SEQ * SEQ + (size_t)row * SEQ + col)
                        = make_float2(v0, v1);
                } else {  // mode 4
                    int b = z >> 4, h = z & (NH - 1);
                    size_t base = ((size_t)b * SEQ + row) * DIM + h * HDIM + col;
#pragma unroll
                    for (int e = 0; e < 2; e++) {
                        float v = e ? v1 : v0;
                        __nv_bfloat16 hi = __float2bfloat16(v);
                        outH[base + e] = hi;
                        outL[base + e] = __float2bfloat16(v - __bfloat162float(hi));
                    }
                }
            }
}

// ---------------- softmax (fp32 in, bf16 hi/lo out) ----------------
__global__ __launch_bounds__(256) void softmax_kernel() {
    const float* p = g_S + (size_t)blockIdx.x * SEQ;
    __nv_bfloat16* ph = g_Ph + (size_t)blockIdx.x * SEQ;
    __nv_bfloat16* pl = g_Pl + (size_t)blockIdx.x * SEQ;
    int tid = threadIdx.x, wid = tid >> 5, lid = tid & 31;
    __shared__ float sred[8];

    float v[8];
    float mx = -1e30f;
#pragma unroll
    for (int i = 0; i < 8; i++) { v[i] = p[tid + i * 256]; mx = fmaxf(mx, v[i]); }
#pragma unroll
    for (int o = 16; o > 0; o >>= 1) mx = fmaxf(mx, __shfl_xor_sync(0xffffffffu, mx, o));
    if (lid == 0) sred[wid] = mx;
    __syncthreads();
    if (wid == 0) {
        float t2 = sred[lid & 7];
#pragma unroll
        for (int o = 4; o > 0; o >>= 1) t2 = fmaxf(t2, __shfl_xor_sync(0xffffffffu, t2, o));
        if (lid == 0) sred[0] = t2;
    }
    __syncthreads();
    mx = sred[0];
    __syncthreads();
    float sum = 0.f;
#pragma unroll
    for (int i = 0; i < 8; i++) { v[i] = __expf(v[i] - mx); sum += v[i]; }
#pragma unroll
    for (int o = 16; o > 0; o >>= 1) sum += __shfl_xor_sync(0xffffffffu, sum, o);
    if (lid == 0) sred[wid] = sum;
    __syncthreads();
    if (wid == 0) {
        float t2 = sred[lid & 7];
#pragma unroll
        for (int o = 4; o > 0; o >>= 1) t2 += __shfl_xor_sync(0xffffffffu, t2, o);
        if (lid == 0) sred[0] = t2;
    }
    __syncthreads();
    float inv = 1.0f / sred[0];
#pragma unroll
    for (int i = 0; i < 8; i++) {
        float w = v[i] * inv;
        __nv_bfloat16 hi = __float2bfloat16(w);
        ph[tid + i * 256] = hi;
        pl[tid + i * 256] = __float2bfloat16(w - __bfloat162float(hi));
    }
}

// ---------------- host ----------------
static void* sym(const void* s) { void* p; cudaGetSymbolAddress(&p, s); return p; }

extern "C" void kernel_launch(void* const* d_in, const int* in_sizes, int n_in,
                              void* d_out, int out_size)
{
    const float* x  = (const float*)d_in[0];
    const float* Wq = (const float*)d_in[1];
    const float* bq = (const float*)d_in[2];
    const float* Wk = (const float*)d_in[3];
    const float* bk = (const float*)d_in[4];
    const float* Wv = (const float*)d_in[5];
    const float* bv = (const float*)d_in[6];
    const float* Wo = (const float*)d_in[7];
    const float* bo = (const float*)d_in[8];
    float* out = (float*)d_out;

    constexpr int SMEM128 = 2 * (2 * 128 * 80 + 2 * 128 * 80);  // 81920
    constexpr int SMEM64  = 2 * (2 * 128 * 80 + 2 * 64 * 80);   // 61440
    cudaFuncSetAttribute(gemm_kernel<128>, cudaFuncAttributeMaxDynamicSharedMemorySize, SMEM128);
    cudaFuncSetAttribute(gemm_kernel<64>,  cudaFuncAttributeMaxDynamicSharedMemorySize, SMEM64);

    __nv_bfloat16 *xh = (__nv_bfloat16*)sym(g_xh), *xl = (__nv_bfloat16*)sym(g_xl);
    __nv_bfloat16 *wqh = (__nv_bfloat16*)sym(g_Wqh), *wql = (__nv_bfloat16*)sym(g_Wql);
    __nv_bfloat16 *wkh = (__nv_bfloat16*)sym(g_Wkh), *wkl = (__nv_bfloat16*)sym(g_Wkl);
    __nv_bfloat16 *wvh = (__nv_bfloat16*)sym(g_Wvh), *wvl = (__nv_bfloat16*)sym(g_Wvl);
    __nv_bfloat16 *woh = (__nv_bfloat16*)sym(g_Woh), *wol = (__nv_bfloat16*)sym(g_Wol);
    __nv_bfloat16 *qh = (__nv_bfloat16*)sym(g_Qh), *ql = (__nv_bfloat16*)sym(g_Ql);
    __nv_bfloat16 *kh = (__nv_bfloat16*)sym(g_Kh), *kl = (__nv_bfloat16*)sym(g_Kl);
    __nv_bfloat16 *vth = (__nv_bfloat16*)sym(g_Vth), *vtl = (__nv_bfloat16*)sym(g_Vtl);
    __nv_bfloat16 *pwh = (__nv_bfloat16*)sym(g_Ph), *pwl = (__nv_bfloat16*)sym(g_Pl);
    __nv_bfloat16 *ah = (__nv_bfloat16*)sym(g_Ah), *al = (__nv_bfloat16*)sym(g_Al);
    float* Sf = (float*)sym(g_S);

    split_kernel<<<(MROWS * DIM + 255) / 256, 256>>>(x, xh, xl, MROWS * DIM);
    dim3 wg(DIM / 32, DIM / 32);
    wsplit_kernel<<<wg, 256>>>(Wq, wqh, wql);
    wsplit_kernel<<<wg, 256>>>(Wk, wkh, wkl);
    wsplit_kernel<<<wg, 256>>>(Wv, wvh, wvl);
    wsplit_kernel<<<wg, 256>>>(Wo, woh, wol);

    dim3 blk(256);
    dim3 gproj(DIM / 128, MROWS / 128, 1);  // 8 x 32

    gemm_kernel<128><<<gproj, blk, SMEM128>>>(xh, xl, DIM, 0, wqh, wql, DIM, 0,
        bq, 0.125f, DIM, 0, qh, ql, nullptr);
    gemm_kernel<128><<<gproj, blk, SMEM128>>>(xh, xl, DIM, 0, wkh, wkl, DIM, 0,
        bk, 1.0f, DIM, 0, kh, kl, nullptr);
    gemm_kernel<128><<<gproj, blk, SMEM128>>>(xh, xl, DIM, 0, wvh, wvl, DIM, 0,
        bv, 1.0f, DIM, 1, vth, vtl, nullptr);

    // scores = Qs @ K^T  (per head, K=64)
    gemm_kernel<128><<<dim3(SEQ / 128, SEQ / 128, BH), blk, SMEM128>>>(
        qh, ql, HDIM, (long)SEQ * HDIM, kh, kl, HDIM, (long)SEQ * HDIM,
        nullptr, 1.0f, HDIM, 3, nullptr, nullptr, Sf);

    softmax_kernel<<<BH * SEQ, 256>>>();

    // attn = P @ V^T  (N = 64)
    gemm_kernel<64><<<dim3(1, SEQ / 128, BH), blk, SMEM64>>>(
        pwh, pwl, SEQ, (long)SEQ * SEQ, vth, vtl, SEQ, (long)HDIM * SEQ,
        nullptr, 1.0f, SEQ, 4, ah, al, nullptr);

    gemm_kernel<128><<<gproj, blk, SMEM128>>>(ah, al, DIM, 0, woh, wol, DIM, 0,
        bo, 1.0f, DIM, 2, nullptr, nullptr, out);
}